// round 2
// baseline (speedup 1.0000x reference)
#include <cuda_runtime.h>
#include <math.h>

// Problem constants
#define Bsz 16384
#define Dd  1024
#define Rr  64
#define Ee  4
#define Ll  3
#define ER  (Ee*Rr)        // 256

// Scratch (device globals — no allocation allowed)
__device__ float g_xl[Bsz * Dd];
__device__ float g_t1[Bsz * ER];
__device__ float g_s [Bsz * ER];

#define BM 128
#define BN 128
#define BK 16

typedef unsigned long long u64;

__device__ __forceinline__ u64 dupf(float a) {
    u64 r;
    unsigned ai = __float_as_uint(a);
    asm("mov.b64 %0, {%1, %1};" : "=l"(r) : "r"(ai));
    return r;
}
__device__ __forceinline__ void ffma2(u64& acc, u64 a, u64 b) {
    asm("fma.rn.f32x2 %0, %1, %2, %0;" : "+l"(acc) : "l"(a), "l"(b));
}
__device__ __forceinline__ float2 unpk(u64 v) {
    unsigned lo, hi;
    asm("mov.b64 {%0, %1}, %2;" : "=r"(lo), "=r"(hi) : "l"(v));
    return make_float2(__uint_as_float(lo), __uint_as_float(hi));
}

// ---------------------------------------------------------------------------
// GEMM1: t1[B,256] = tanh( xl[B,1024] @ Vl[256,1024]^T )   (NT, both K-contig)
// ---------------------------------------------------------------------------
__global__ __launch_bounds__(256)
void gemm1_tanh(const float* __restrict__ A,    // xl [M, 1024]
                const float* __restrict__ Bw)   // V layer [256, 1024]
{
    const int K = Dd;
    const int N = ER;
    __shared__ float As[2][BK][BM];
    __shared__ float Bs2[2][BK][BN];

    const int m0 = blockIdx.y * BM;
    const int n0 = blockIdx.x * BN;
    const int tid = threadIdx.x;
    const int tr = (tid >> 4) << 3;
    const int tc = (tid & 15) << 3;

    const int lr  = tid >> 2;          // 0..63  (chunk row, +64 for p=1)
    const int lc4 = (tid & 3) << 2;    // 0,4,8,12
    const float* gA0 = A  + (size_t)(m0 + lr) * K + lc4;
    const float* gA1 = A  + (size_t)(m0 + lr + 64) * K + lc4;
    const float* gB0 = Bw + (size_t)(n0 + lr) * K + lc4;
    const float* gB1 = Bw + (size_t)(n0 + lr + 64) * K + lc4;

    u64 acc[8][4];
    #pragma unroll
    for (int i = 0; i < 8; i++)
        #pragma unroll
        for (int j = 0; j < 4; j++) acc[i][j] = 0ull;

    // prologue: tile 0
    {
        float4 va0 = *(const float4*)(gA0);
        float4 va1 = *(const float4*)(gA1);
        float4 vb0 = *(const float4*)(gB0);
        float4 vb1 = *(const float4*)(gB1);
        As[0][lc4+0][lr]     = va0.x; As[0][lc4+1][lr]     = va0.y;
        As[0][lc4+2][lr]     = va0.z; As[0][lc4+3][lr]     = va0.w;
        As[0][lc4+0][lr+64]  = va1.x; As[0][lc4+1][lr+64]  = va1.y;
        As[0][lc4+2][lr+64]  = va1.z; As[0][lc4+3][lr+64]  = va1.w;
        Bs2[0][lc4+0][lr]    = vb0.x; Bs2[0][lc4+1][lr]    = vb0.y;
        Bs2[0][lc4+2][lr]    = vb0.z; Bs2[0][lc4+3][lr]    = vb0.w;
        Bs2[0][lc4+0][lr+64] = vb1.x; Bs2[0][lc4+1][lr+64] = vb1.y;
        Bs2[0][lc4+2][lr+64] = vb1.z; Bs2[0][lc4+3][lr+64] = vb1.w;
    }
    __syncthreads();

    int cur = 0;
    #pragma unroll 1
    for (int k0 = BK; k0 < K; k0 += BK) {
        float4 va0 = *(const float4*)(gA0 + k0);
        float4 va1 = *(const float4*)(gA1 + k0);
        float4 vb0 = *(const float4*)(gB0 + k0);
        float4 vb1 = *(const float4*)(gB1 + k0);

        #pragma unroll
        for (int k = 0; k < BK; k++) {
            float a[8];
            *(float4*)(a)     = *(const float4*)&As[cur][k][tr];
            *(float4*)(a + 4) = *(const float4*)&As[cur][k][tr + 4];
            u64 b2[4];
            *(ulonglong2*)(b2)     = *(const ulonglong2*)&Bs2[cur][k][tc];
            *(ulonglong2*)(b2 + 2) = *(const ulonglong2*)&Bs2[cur][k][tc + 4];
            #pragma unroll
            for (int i = 0; i < 8; i++) {
                u64 ad = dupf(a[i]);
                #pragma unroll
                for (int j = 0; j < 4; j++) ffma2(acc[i][j], ad, b2[j]);
            }
        }

        const int nxt = cur ^ 1;
        As[nxt][lc4+0][lr]     = va0.x; As[nxt][lc4+1][lr]     = va0.y;
        As[nxt][lc4+2][lr]     = va0.z; As[nxt][lc4+3][lr]     = va0.w;
        As[nxt][lc4+0][lr+64]  = va1.x; As[nxt][lc4+1][lr+64]  = va1.y;
        As[nxt][lc4+2][lr+64]  = va1.z; As[nxt][lc4+3][lr+64]  = va1.w;
        Bs2[nxt][lc4+0][lr]    = vb0.x; Bs2[nxt][lc4+1][lr]    = vb0.y;
        Bs2[nxt][lc4+2][lr]    = vb0.z; Bs2[nxt][lc4+3][lr]    = vb0.w;
        Bs2[nxt][lc4+0][lr+64] = vb1.x; Bs2[nxt][lc4+1][lr+64] = vb1.y;
        Bs2[nxt][lc4+2][lr+64] = vb1.z; Bs2[nxt][lc4+3][lr+64] = vb1.w;
        __syncthreads();
        cur = nxt;
    }
    // last tile
    #pragma unroll
    for (int k = 0; k < BK; k++) {
        float a[8];
        *(float4*)(a)     = *(const float4*)&As[cur][k][tr];
        *(float4*)(a + 4) = *(const float4*)&As[cur][k][tr + 4];
        u64 b2[4];
        *(ulonglong2*)(b2)     = *(const ulonglong2*)&Bs2[cur][k][tc];
        *(ulonglong2*)(b2 + 2) = *(const ulonglong2*)&Bs2[cur][k][tc + 4];
        #pragma unroll
        for (int i = 0; i < 8; i++) {
            u64 ad = dupf(a[i]);
            #pragma unroll
            for (int j = 0; j < 4; j++) ffma2(acc[i][j], ad, b2[j]);
        }
    }

    #pragma unroll
    for (int i = 0; i < 8; i++) {
        const size_t row = (size_t)(m0 + tr + i);
        #pragma unroll
        for (int j4 = 0; j4 < 2; j4++) {
            float2 p0 = unpk(acc[i][j4*2+0]);
            float2 p1 = unpk(acc[i][j4*2+1]);
            float4 v;
            v.x = tanhf(p0.x); v.y = tanhf(p0.y);
            v.z = tanhf(p1.x); v.w = tanhf(p1.y);
            *(float4*)(g_t1 + row * N + n0 + tc + j4*4) = v;
        }
    }
}

// ---------------------------------------------------------------------------
// gate_mix: softmax gate + s = g_e * tanh(C_e @ t1_e), one warp per row
// ---------------------------------------------------------------------------
#define CSTR 66   // even row stride for 8B-aligned pair loads (2-way conflict ok)
__global__ __launch_bounds__(256)
void gate_mix(const float* __restrict__ xl,
              const float* __restrict__ Cw,   // layer C [E,R,R]
              const float* __restrict__ gw)   // gates_w [E, D]
{
    extern __shared__ float sm[];
    float* Cs  = sm;                       // 4 * 64 * CSTR
    float* t1s = sm + 4 * Rr * CSTR;       // 8 * 256

    const int tid = threadIdx.x;
    for (int idx = tid; idx < Ee * Rr * Rr; idx += 256) {
        int e = idx >> 12, rem = idx & 4095, r = rem >> 6, s = rem & 63;
        Cs[(e * Rr + r) * CSTR + s] = Cw[idx];
    }
    const int b0 = blockIdx.x << 3;
    for (int idx = tid; idx < 8 * 256; idx += 256) {
        int rl = idx >> 8, j = idx & 255;
        t1s[idx] = g_t1[(size_t)(b0 + rl) * ER + j];
    }
    __syncthreads();

    const int w = tid >> 5, lane = tid & 31;
    const int b = b0 + w;
    const float* xr = xl + (size_t)b * Dd;

    float s0 = 0.f, s1 = 0.f, s2 = 0.f, s3 = 0.f;
    for (int d = lane; d < Dd; d += 32) {
        float xv = xr[d];
        s0 = fmaf(xv, gw[d],          s0);
        s1 = fmaf(xv, gw[Dd + d],     s1);
        s2 = fmaf(xv, gw[2 * Dd + d], s2);
        s3 = fmaf(xv, gw[3 * Dd + d], s3);
    }
    #pragma unroll
    for (int o = 16; o; o >>= 1) {
        s0 += __shfl_xor_sync(0xffffffffu, s0, o);
        s1 += __shfl_xor_sync(0xffffffffu, s1, o);
        s2 += __shfl_xor_sync(0xffffffffu, s2, o);
        s3 += __shfl_xor_sync(0xffffffffu, s3, o);
    }
    float mx = fmaxf(fmaxf(s0, s1), fmaxf(s2, s3));
    float e0 = expf(s0 - mx), e1 = expf(s1 - mx), e2 = expf(s2 - mx), e3 = expf(s3 - mx);
    float inv = 1.f / (e0 + e1 + e2 + e3);
    float gg[4] = { e0 * inv, e1 * inv, e2 * inv, e3 * inv };

    const float* t1r = t1s + w * ER;
    #pragma unroll
    for (int i = 0; i < 8; i++) {
        int j = (i << 5) + lane;
        int e = j >> 6, r = j & 63;
        const u64* cr = (const u64*)(Cs + (e * Rr + r) * CSTR);
        const u64* tv = (const u64*)(t1r + (e << 6));
        u64 acc = 0ull;
        #pragma unroll
        for (int s = 0; s < 32; s++) ffma2(acc, cr[s], tv[s]);
        float2 p = unpk(acc);
        g_s[(size_t)b * ER + j] = gg[e] * tanhf(p.x + p.y);
    }
}

// ---------------------------------------------------------------------------
// GEMM2: out[B,1024] = xl + x0 * ( bias + s[B,256] @ W2 ),
//   W2[k=e*64+r][n=d] = U[e, d, r]
// ---------------------------------------------------------------------------
__global__ __launch_bounds__(256)
void gemm2_combine(const float* __restrict__ Uw,     // layer U [E, D, R]
                   const float* __restrict__ xl_in,
                   const float* __restrict__ x0,
                   const float* __restrict__ bias,   // [D]
                   float* __restrict__ out)
{
    const int K = ER;       // 256
    const int N = Dd;       // 1024
    __shared__ float As[2][BK][BM];
    __shared__ float Bs2[2][BK][BN];

    const int m0 = blockIdx.y * BM;
    const int n0 = blockIdx.x * BN;
    const int tid = threadIdx.x;
    const int tr = (tid >> 4) << 3;
    const int tc = (tid & 15) << 3;

    const int lr  = tid >> 2;
    const int lc4 = (tid & 3) << 2;
    const float* gA0 = g_s + (size_t)(m0 + lr) * K + lc4;
    const float* gA1 = g_s + (size_t)(m0 + lr + 64) * K + lc4;

    u64 acc[8][4];
    #pragma unroll
    for (int i = 0; i < 8; i++)
        #pragma unroll
        for (int j = 0; j < 4; j++) acc[i][j] = 0ull;

    // B chunk loader: k-tile element (k0+lc4 .. +3) for rows n0+lr, n0+lr+64
    // addr = Uw[e*(D*R) + n*R + rr],  e=(k)>>6, rr=k&63 (lc4 block never crosses 64)
    {
        const int k = lc4;
        const int e = k >> 6, rr = k & 63;
        const float* gB = Uw + (size_t)e * (Dd * Rr) + rr;
        float4 va0 = *(const float4*)(gA0);
        float4 va1 = *(const float4*)(gA1);
        float4 vb0 = *(const float4*)(gB + (size_t)(n0 + lr) * Rr);
        float4 vb1 = *(const float4*)(gB + (size_t)(n0 + lr + 64) * Rr);
        As[0][lc4+0][lr]     = va0.x; As[0][lc4+1][lr]     = va0.y;
        As[0][lc4+2][lr]     = va0.z; As[0][lc4+3][lr]     = va0.w;
        As[0][lc4+0][lr+64]  = va1.x; As[0][lc4+1][lr+64]  = va1.y;
        As[0][lc4+2][lr+64]  = va1.z; As[0][lc4+3][lr+64]  = va1.w;
        Bs2[0][lc4+0][lr]    = vb0.x; Bs2[0][lc4+1][lr]    = vb0.y;
        Bs2[0][lc4+2][lr]    = vb0.z; Bs2[0][lc4+3][lr]    = vb0.w;
        Bs2[0][lc4+0][lr+64] = vb1.x; Bs2[0][lc4+1][lr+64] = vb1.y;
        Bs2[0][lc4+2][lr+64] = vb1.z; Bs2[0][lc4+3][lr+64] = vb1.w;
    }
    __syncthreads();

    int cur = 0;
    #pragma unroll 1
    for (int k0 = BK; k0 < K; k0 += BK) {
        const int k = k0 + lc4;
        const int e = k >> 6, rr = k & 63;
        const float* gB = Uw + (size_t)e * (Dd * Rr) + rr;
        float4 va0 = *(const float4*)(gA0 + k0);
        float4 va1 = *(const float4*)(gA1 + k0);
        float4 vb0 = *(const float4*)(gB + (size_t)(n0 + lr) * Rr);
        float4 vb1 = *(const float4*)(gB + (size_t)(n0 + lr + 64) * Rr);

        #pragma unroll
        for (int kk = 0; kk < BK; kk++) {
            float a[8];
            *(float4*)(a)     = *(const float4*)&As[cur][kk][tr];
            *(float4*)(a + 4) = *(const float4*)&As[cur][kk][tr + 4];
            u64 b2[4];
            *(ulonglong2*)(b2)     = *(const ulonglong2*)&Bs2[cur][kk][tc];
            *(ulonglong2*)(b2 + 2) = *(const ulonglong2*)&Bs2[cur][kk][tc + 4];
            #pragma unroll
            for (int i = 0; i < 8; i++) {
                u64 ad = dupf(a[i]);
                #pragma unroll
                for (int j = 0; j < 4; j++) ffma2(acc[i][j], ad, b2[j]);
            }
        }

        const int nxt = cur ^ 1;
        As[nxt][lc4+0][lr]     = va0.x; As[nxt][lc4+1][lr]     = va0.y;
        As[nxt][lc4+2][lr]     = va0.z; As[nxt][lc4+3][lr]     = va0.w;
        As[nxt][lc4+0][lr+64]  = va1.x; As[nxt][lc4+1][lr+64]  = va1.y;
        As[nxt][lc4+2][lr+64]  = va1.z; As[nxt][lc4+3][lr+64]  = va1.w;
        Bs2[nxt][lc4+0][lr]    = vb0.x; Bs2[nxt][lc4+1][lr]    = vb0.y;
        Bs2[nxt][lc4+2][lr]    = vb0.z; Bs2[nxt][lc4+3][lr]    = vb0.w;
        Bs2[nxt][lc4+0][lr+64] = vb1.x; Bs2[nxt][lc4+1][lr+64] = vb1.y;
        Bs2[nxt][lc4+2][lr+64] = vb1.z; Bs2[nxt][lc4+3][lr+64] = vb1.w;
        __syncthreads();
        cur = nxt;
    }
    #pragma unroll
    for (int kk = 0; kk < BK; kk++) {
        float a[8];
        *(float4*)(a)     = *(const float4*)&As[cur][kk][tr];
        *(float4*)(a + 4) = *(const float4*)&As[cur][kk][tr + 4];
        u64 b2[4];
        *(ulonglong2*)(b2)     = *(const ulonglong2*)&Bs2[cur][kk][tc];
        *(ulonglong2*)(b2 + 2) = *(const ulonglong2*)&Bs2[cur][kk][tc + 4];
        #pragma unroll
        for (int i = 0; i < 8; i++) {
            u64 ad = dupf(a[i]);
            #pragma unroll
            for (int j = 0; j < 4; j++) ffma2(acc[i][j], ad, b2[j]);
        }
    }

    #pragma unroll
    for (int i = 0; i < 8; i++) {
        const size_t row = (size_t)(m0 + tr + i);
        #pragma unroll
        for (int j4 = 0; j4 < 2; j4++) {
            const int col = n0 + tc + j4*4;
            const size_t idx = row * N + col;
            float2 p0 = unpk(acc[i][j4*2+0]);
            float2 p1 = unpk(acc[i][j4*2+1]);
            float4 xv  = *(const float4*)(xl_in + idx);
            float4 x0v = *(const float4*)(x0 + idx);
            float4 bv  = *(const float4*)(bias + col);
            float4 o;
            o.x = fmaf(x0v.x, bv.x + p0.x, xv.x);
            o.y = fmaf(x0v.y, bv.y + p0.y, xv.y);
            o.z = fmaf(x0v.z, bv.z + p1.x, xv.z);
            o.w = fmaf(x0v.w, bv.w + p1.y, xv.w);
            *(float4*)(out + idx) = o;
        }
    }
}

// ---------------------------------------------------------------------------
// Launch
// ---------------------------------------------------------------------------
extern "C" void kernel_launch(void* const* d_in, const int* in_sizes, int n_in,
                              void* d_out, int out_size)
{
    const float* x    = (const float*)d_in[0];   // [B, D]
    const float* U    = (const float*)d_in[1];   // [L, E, D, R]
    const float* V    = (const float*)d_in[2];   // [L, E, R, D]
    const float* C    = (const float*)d_in[3];   // [L, E, R, R]
    const float* bias = (const float*)d_in[4];   // [L, D]
    const float* gw   = (const float*)d_in[5];   // [E, D]
    float* out = (float*)d_out;

    float* p_xl = nullptr;
    cudaGetSymbolAddress((void**)&p_xl, g_xl);

    const int smem_gate = (4 * Rr * CSTR + 8 * 256) * (int)sizeof(float);
    cudaFuncSetAttribute(gate_mix, cudaFuncAttributeMaxDynamicSharedMemorySize, smem_gate);

    const int EB = Ee * Rr * Dd;   // 262144 per-layer stride for U and V

    dim3 g1(ER / BN, Bsz / BM);    // (2, 128)
    dim3 g2(Dd / BN, Bsz / BM);    // (8, 128)

    for (int l = 0; l < Ll; l++) {
        const float* xin  = (l == 0)      ? x   : p_xl;
        float*       xout = (l == Ll - 1) ? out : p_xl;
        gemm1_tanh   <<<g1, 256>>>(xin, V + (size_t)l * EB);
        gate_mix     <<<Bsz / 8, 256, smem_gate>>>(xin, C + (size_t)l * Ee * Rr * Rr, gw);
        gemm2_combine<<<g2, 256>>>(U + (size_t)l * EB, xin, x, bias + (size_t)l * Dd, xout);
    }
}

// round 4
// speedup vs baseline: 1.8642x; 1.8642x over previous
#include <cuda_runtime.h>
#include <cuda_bf16.h>
#include <math.h>

#define Bsz 16384
#define Dd  1024
#define Rr  64
#define Ee  4
#define Ll  3
#define ER  256

typedef unsigned u32;
typedef unsigned long long u64;
typedef __nv_bfloat16 bf16;

// tcgen05 is arch-specific: only compile it for sm_103a/sm_100a (or family)
// device passes. The generic compute_103 PTX pass gets a correct SIMT
// fallback (never selected at runtime when the sm_103a cubin is present).
#if defined(__CUDA_ARCH_FEAT_SM103_ALL) || defined(__CUDA_ARCH_FEAT_SM100_ALL) || \
    defined(__CUDA_ARCH_FAMILY_SPECIFIC__) || defined(__CUDA_ARCH_SPECIFIC__)
#define TC_OK 1
#else
#define TC_OK 0
#endif

// ---------------- scratch (device globals; no allocs allowed) ----------------
__device__ float g_xl [Bsz * Dd];      // fp32 activation (for gate + residual)
__device__ bf16  g_xh [Bsz * Dd];      // bf16 hi of xl
__device__ bf16  g_xlo[Bsz * Dd];      // bf16 lo of xl
__device__ float g_t1 [Bsz * ER];      // tanh(V xl)
__device__ bf16  g_sh [Bsz * ER];      // hi of s
__device__ bf16  g_sl [Bsz * ER];      // lo of s
__device__ bf16  g_V2 [ER * 3 * Dd];   // packed V'': [256][3072] = [Vhi,Vlo,Vhi]
__device__ bf16  g_U2 [Dd * 3 * ER];   // packed U'': [1024][768] = [Uhi,Ulo,Uhi]

// ---------------- PTX helpers ----------------
__device__ __forceinline__ u32 smem_u32(const void* p) {
    u32 a;
    asm("{ .reg .u64 t; cvta.to.shared.u64 t, %1; cvt.u32.u64 %0, t; }" : "=r"(a) : "l"(p));
    return a;
}
__device__ __forceinline__ u32 elect1() {
    u32 p;
    asm volatile("{\n\t.reg .pred p;\n\telect.sync _|p, 0xFFFFFFFF;\n\tselp.b32 %0, 1, 0, p;\n\t}" : "=r"(p));
    return p;
}
#define TC_ALLOC(sa, n)   asm volatile("tcgen05.alloc.cta_group::1.sync.aligned.shared::cta.b32 [%0], %1;" :: "r"(sa), "r"((u32)(n)) : "memory")
#define TC_RELINQ()       asm volatile("tcgen05.relinquish_alloc_permit.cta_group::1.sync.aligned;")
#define TC_DEALLOC(t, n)  asm volatile("tcgen05.dealloc.cta_group::1.sync.aligned.b32 %0, %1;" :: "r"(t), "r"((u32)(n)))
#define TC_COMMIT(mb)     asm volatile("tcgen05.commit.cta_group::1.mbarrier::arrive::one.shared::cluster.b64 [%0];" :: "r"(mb) : "memory")
#define TC_FENCE_AFTER()  asm volatile("tcgen05.fence::after_thread_sync;" ::: "memory")
#define TC_WAIT_LD()      asm volatile("tcgen05.wait::ld.sync.aligned;" ::: "memory")
#define FENCE_ASYNC()     asm volatile("fence.proxy.async.shared::cta;" ::: "memory")
#define MBAR_INIT(mb, c)  asm volatile("mbarrier.init.shared.b64 [%0], %1;" :: "r"(mb), "r"((u32)(c)) : "memory")

__device__ __forceinline__ void mbar_wait(u32 mb, u32 parity) {
    asm volatile(
        "{\n\t.reg .pred P1;\n\t"
        "WAIT_LOOP_%=:\n\t"
        "mbarrier.try_wait.parity.acquire.cta.shared::cta.b64 P1, [%0], %1, 0x989680;\n\t"
        "@P1 bra.uni WAIT_DONE_%=;\n\t"
        "bra.uni WAIT_LOOP_%=;\n\t"
        "WAIT_DONE_%=:\n\t}"
        :: "r"(mb), "r"(parity) : "memory");
}
__device__ __forceinline__ void mma_f16_ss(u32 d, u64 ad, u64 bd, u32 idesc, u32 accum) {
#if TC_OK
    asm volatile(
        "{\n\t.reg .pred p;\n\tsetp.ne.u32 p, %4, 0;\n\t"
        "tcgen05.mma.cta_group::1.kind::f16 [%0], %1, %2, %3, {%5,%5,%5,%5}, p;\n\t}"
        :: "r"(d), "l"(ad), "l"(bd), "r"(idesc), "r"(accum), "r"(0u) : "memory");
#endif
}
#define LDTM32(r, a) \
    asm volatile("tcgen05.ld.sync.aligned.32x32b.x32.b32 " \
        "{%0,%1,%2,%3,%4,%5,%6,%7,%8,%9,%10,%11,%12,%13,%14,%15," \
        "%16,%17,%18,%19,%20,%21,%22,%23,%24,%25,%26,%27,%28,%29,%30,%31}, [%32];" \
        : "=r"((r)[0]),"=r"((r)[1]),"=r"((r)[2]),"=r"((r)[3]),"=r"((r)[4]),"=r"((r)[5]),"=r"((r)[6]),"=r"((r)[7]), \
          "=r"((r)[8]),"=r"((r)[9]),"=r"((r)[10]),"=r"((r)[11]),"=r"((r)[12]),"=r"((r)[13]),"=r"((r)[14]),"=r"((r)[15]), \
          "=r"((r)[16]),"=r"((r)[17]),"=r"((r)[18]),"=r"((r)[19]),"=r"((r)[20]),"=r"((r)[21]),"=r"((r)[22]),"=r"((r)[23]), \
          "=r"((r)[24]),"=r"((r)[25]),"=r"((r)[26]),"=r"((r)[27]),"=r"((r)[28]),"=r"((r)[29]),"=r"((r)[30]),"=r"((r)[31]) \
        : "r"(a))

// SW128 K-major smem descriptor (version=1, layout SW128, LBO=1, SBO=64)
__device__ __forceinline__ u64 smem_desc(u32 addr) {
    const u64 base = (u64(2) << 61) | (u64(1) << 46) | (u64(64) << 32) | (u64(1) << 16);
    return base | ((u64)(addr >> 4) & 0x3FFF);
}
__device__ __forceinline__ u32 sw128(u32 off) { return off ^ ((off >> 3) & 0x70); }

// idesc: fp32 accum, bf16 A/B, N=256, M=128
#define IDESC_256 ((1u<<4) | (1u<<7) | (1u<<10) | ((256u/8)<<17) | ((128u/16)<<24))

// smem layout (dynamic): [0] tmem ptr, [16],[32] mbars, A bufs @1024/17408 (16KB each),
// B bufs @33792/66560 (32KB each). total 99328 bytes.
#define SM_TOTAL 99328
#define SM_A(b)  (1024 + (b) * 16384)
#define SM_B(b)  (33792 + (b) * 32768)

// ---------------------------------------------------------------------------
// prep kernels
// ---------------------------------------------------------------------------
__global__ void conv_x(const float* __restrict__ x) {
    int i = (blockIdx.x * 256 + threadIdx.x) * 4;
    float4 v = *(const float4*)(x + i);
    float f[4] = {v.x, v.y, v.z, v.w};
    #pragma unroll
    for (int k = 0; k < 4; k++) {
        bf16 h = __float2bfloat16(f[k]);
        g_xh[i + k]  = h;
        g_xlo[i + k] = __float2bfloat16(f[k] - __bfloat162float(h));
    }
}

__global__ void pack_V(const float* __restrict__ Vl) {   // [256][1024] -> g_V2 [256][3072]
    int idx = blockIdx.x * 256 + threadIdx.x;            // grid 3072
    int n = idx / 3072, kk = idx % 3072;
    int seg = kk >> 10, k = kk & 1023;
    float v = Vl[n * 1024 + k];
    bf16 h = __float2bfloat16(v);
    g_V2[idx] = (seg == 1) ? __float2bfloat16(v - __bfloat162float(h)) : h;
}

__global__ void pack_U(const float* __restrict__ Ul) {   // U[e][d][r] -> g_U2 [1024][768]
    int idx = blockIdx.x * 256 + threadIdx.x;            // grid 3072
    int n = idx / 768, kk = idx % 768;
    int seg = kk >> 8, k = kk & 255;
    int e = k >> 6, r = k & 63;
    float v = Ul[e * (Dd * Rr) + n * Rr + r];
    bf16 h = __float2bfloat16(v);
    g_U2[idx] = (seg == 1) ? __float2bfloat16(v - __bfloat162float(h)) : h;
}

// ---------------------------------------------------------------------------
// GEMM1 (tensor): t1 = tanh( A''[16384,3072] @ V''[256,3072]^T ), tile 128x256
// ---------------------------------------------------------------------------
__global__ void __launch_bounds__(256, 1)
gemm1_tc() {
#if TC_OK
    extern __shared__ char smem[];
    const u32 sb = smem_u32(smem);
    const int tid = threadIdx.x, wid = tid >> 5, lane = tid & 31;
    const int m0 = blockIdx.x * 128;

    if (wid == 0) { TC_ALLOC(sb, 256); TC_RELINQ(); }
    if (tid == 0) { MBAR_INIT(sb + 16, 1); MBAR_INIT(sb + 32, 1); }
    __syncthreads();
    u32 tmem;
    asm volatile("ld.shared.b32 %0, [%1];" : "=r"(tmem) : "r"(sb));

    u32 ph[2] = {0, 0};
    #pragma unroll 1
    for (int t = 0; t < 48; t++) {
        const int b = t & 1;
        if (t >= 2) { mbar_wait(sb + 16 + b * 16, ph[b]); ph[b] ^= 1; }
        const int seg = t >> 4, kc = (t & 15) << 6;
        const bf16* As = (seg < 2) ? g_xh : g_xlo;
        #pragma unroll
        for (int i = 0; i < 4; i++) {
            int slot = tid + (i << 8);
            int row = slot >> 3, c8 = (slot & 7) << 3;
            uint4 v = *(const uint4*)(As + (size_t)(m0 + row) * Dd + kc + c8);
            *(uint4*)(smem + SM_A(b) + sw128((row << 7) + (c8 << 1))) = v;
        }
        #pragma unroll
        for (int i = 0; i < 8; i++) {
            int slot = tid + (i << 8);
            int row = slot >> 3, c8 = (slot & 7) << 3;
            uint4 v = *(const uint4*)(g_V2 + (size_t)row * 3072 + (t << 6) + c8);
            *(uint4*)(smem + SM_B(b) + sw128((row << 7) + (c8 << 1))) = v;
        }
        FENCE_ASYNC();
        __syncthreads();
        if (wid == 0 && elect1()) {
            u64 ad = smem_desc(sb + SM_A(b));
            u64 bd = smem_desc(sb + SM_B(b));
            #pragma unroll
            for (int k = 0; k < 4; k++)
                mma_f16_ss(tmem, ad + k * 2, bd + k * 2, IDESC_256, (t > 0) || (k > 0));
            TC_COMMIT(sb + 16 + b * 16);
        }
    }
    mbar_wait(sb + 16, ph[0]);
    mbar_wait(sb + 32, ph[1]);
    TC_FENCE_AFTER();
    __syncthreads();

    // epilogue: tanh + transpose to coalesced stores
    const int sp = wid & 3;
    const int cbase = (wid >> 2) * 128;
    float* T = (float*)(smem + 1024) + wid * 1056;   // 32x33
    #pragma unroll 1
    for (int j = 0; j < 4; j++) {
        const int cb = cbase + j * 32;
        u32 r[32];
        LDTM32(r, tmem + cb);
        TC_WAIT_LD();
        #pragma unroll
        for (int c = 0; c < 32; c++) T[lane * 33 + c] = tanhf(__uint_as_float(r[c]));
        __syncwarp();
        #pragma unroll
        for (int rr = 0; rr < 32; rr++)
            g_t1[(size_t)(m0 + sp * 32 + rr) * ER + cb + lane] = T[rr * 33 + lane];
        __syncwarp();
    }
    __syncthreads();
    if (wid == 0) TC_DEALLOC(tmem, 256);
#else
    // Generic-arch fallback (not used at runtime on GB300; kept correct).
    const int tid = threadIdx.x;
    const int m0 = blockIdx.x * 128;
    for (int o = tid; o < 128 * 256; o += 256) {
        int row = o >> 8, col = o & 255;
        const bf16* xh = g_xh  + (size_t)(m0 + row) * Dd;
        const bf16* xo = g_xlo + (size_t)(m0 + row) * Dd;
        const bf16* bv = g_V2  + (size_t)col * 3072;
        float acc = 0.f;
        for (int k = 0; k < Dd; k++) {
            float bh = __bfloat162float(bv[k]);
            float bl = __bfloat162float(bv[1024 + k]);
            acc += __bfloat162float(xh[k]) * (bh + bl) + __bfloat162float(xo[k]) * bh;
        }
        g_t1[(size_t)(m0 + row) * ER + col] = tanhf(acc);
    }
#endif
}

// ---------------------------------------------------------------------------
// gate_mix: softmax gate + s = g_e * tanh(C_e @ t1_e); outputs bf16 hi/lo
// ---------------------------------------------------------------------------
#define CSTR 66
__global__ __launch_bounds__(256)
void gate_mix(const float* __restrict__ xl,
              const float* __restrict__ Cw,
              const float* __restrict__ gw)
{
    extern __shared__ float sm[];
    float* Cs  = sm;
    float* t1s = sm + 4 * Rr * CSTR;

    const int tid = threadIdx.x;
    for (int idx = tid; idx < Ee * Rr * Rr; idx += 256) {
        int e = idx >> 12, rem = idx & 4095, r = rem >> 6, s = rem & 63;
        Cs[(e * Rr + r) * CSTR + s] = Cw[idx];
    }
    const int b0 = blockIdx.x << 3;
    for (int idx = tid; idx < 8 * 256; idx += 256) {
        int rl = idx >> 8, j = idx & 255;
        t1s[idx] = g_t1[(size_t)(b0 + rl) * ER + j];
    }
    __syncthreads();

    const int w = tid >> 5, lane = tid & 31;
    const int b = b0 + w;
    const float* xr = xl + (size_t)b * Dd;

    float s0 = 0.f, s1 = 0.f, s2 = 0.f, s3 = 0.f;
    for (int d = lane; d < Dd; d += 32) {
        float xv = xr[d];
        s0 = fmaf(xv, gw[d],          s0);
        s1 = fmaf(xv, gw[Dd + d],     s1);
        s2 = fmaf(xv, gw[2 * Dd + d], s2);
        s3 = fmaf(xv, gw[3 * Dd + d], s3);
    }
    #pragma unroll
    for (int o = 16; o; o >>= 1) {
        s0 += __shfl_xor_sync(0xffffffffu, s0, o);
        s1 += __shfl_xor_sync(0xffffffffu, s1, o);
        s2 += __shfl_xor_sync(0xffffffffu, s2, o);
        s3 += __shfl_xor_sync(0xffffffffu, s3, o);
    }
    float mx = fmaxf(fmaxf(s0, s1), fmaxf(s2, s3));
    float e0 = expf(s0 - mx), e1 = expf(s1 - mx), e2 = expf(s2 - mx), e3 = expf(s3 - mx);
    float inv = 1.f / (e0 + e1 + e2 + e3);
    float gg[4] = { e0 * inv, e1 * inv, e2 * inv, e3 * inv };

    const float* t1r = t1s + w * ER;
    #pragma unroll
    for (int i = 0; i < 8; i++) {
        int j = (i << 5) + lane;
        int e = j >> 6, r = j & 63;
        const float* cr = Cs + (e * Rr + r) * CSTR;
        const float* tv = t1r + (e << 6);
        float sum = 0.f;
        #pragma unroll
        for (int s = 0; s < 64; s++) sum = fmaf(cr[s], tv[s], sum);
        float val = gg[e] * tanhf(sum);
        bf16 h = __float2bfloat16(val);
        size_t o = (size_t)b * ER + j;
        g_sh[o] = h;
        g_sl[o] = __float2bfloat16(val - __bfloat162float(h));
    }
}

// ---------------------------------------------------------------------------
// GEMM2 (tensor): out = xl + x0*(bias + s''[16384,768] @ U''[1024,768]^T)
// tile 128x256, grid 128*4; also emits bf16 hi/lo of result
// ---------------------------------------------------------------------------
__global__ void __launch_bounds__(256, 1)
gemm2_tc(const float* __restrict__ xl_in,
         const float* __restrict__ x0,
         const float* __restrict__ bias,
         float* __restrict__ out)
{
#if TC_OK
    extern __shared__ char smem[];
    const u32 sb = smem_u32(smem);
    const int tid = threadIdx.x, wid = tid >> 5, lane = tid & 31;
    const int m0 = (blockIdx.x >> 2) * 128;
    const int n0 = (blockIdx.x & 3) * 256;

    if (wid == 0) { TC_ALLOC(sb, 256); TC_RELINQ(); }
    if (tid == 0) { MBAR_INIT(sb + 16, 1); MBAR_INIT(sb + 32, 1); }
    __syncthreads();
    u32 tmem;
    asm volatile("ld.shared.b32 %0, [%1];" : "=r"(tmem) : "r"(sb));

    u32 ph[2] = {0, 0};
    #pragma unroll 1
    for (int t = 0; t < 12; t++) {
        const int b = t & 1;
        if (t >= 2) { mbar_wait(sb + 16 + b * 16, ph[b]); ph[b] ^= 1; }
        const int seg = t >> 2, kc = (t & 3) << 6;
        const bf16* As = (seg < 2) ? g_sh : g_sl;
        #pragma unroll
        for (int i = 0; i < 4; i++) {
            int slot = tid + (i << 8);
            int row = slot >> 3, c8 = (slot & 7) << 3;
            uint4 v = *(const uint4*)(As + (size_t)(m0 + row) * ER + kc + c8);
            *(uint4*)(smem + SM_A(b) + sw128((row << 7) + (c8 << 1))) = v;
        }
        #pragma unroll
        for (int i = 0; i < 8; i++) {
            int slot = tid + (i << 8);
            int row = slot >> 3, c8 = (slot & 7) << 3;
            uint4 v = *(const uint4*)(g_U2 + (size_t)(n0 + row) * 768 + (t << 6) + c8);
            *(uint4*)(smem + SM_B(b) + sw128((row << 7) + (c8 << 1))) = v;
        }
        FENCE_ASYNC();
        __syncthreads();
        if (wid == 0 && elect1()) {
            u64 ad = smem_desc(sb + SM_A(b));
            u64 bd = smem_desc(sb + SM_B(b));
            #pragma unroll
            for (int k = 0; k < 4; k++)
                mma_f16_ss(tmem, ad + k * 2, bd + k * 2, IDESC_256, (t > 0) || (k > 0));
            TC_COMMIT(sb + 16 + b * 16);
        }
    }
    mbar_wait(sb + 16, ph[0]);
    mbar_wait(sb + 32, ph[1]);
    TC_FENCE_AFTER();
    __syncthreads();

    const int sp = wid & 3;
    const int cbase = (wid >> 2) * 128;
    float* T = (float*)(smem + 1024) + wid * 1056;
    #pragma unroll 1
    for (int j = 0; j < 4; j++) {
        const int cb = cbase + j * 32;
        u32 r[32];
        LDTM32(r, tmem + cb);
        TC_WAIT_LD();
        #pragma unroll
        for (int c = 0; c < 32; c++) T[lane * 33 + c] = __uint_as_float(r[c]);
        __syncwarp();
        const int col = n0 + cb + lane;
        const float bv = bias[col];
        #pragma unroll
        for (int rr = 0; rr < 32; rr++) {
            const size_t idx = (size_t)(m0 + sp * 32 + rr) * Dd + col;
            float o = fmaf(x0[idx], bv + T[rr * 33 + lane], xl_in[idx]);
            out[idx] = o;
            bf16 h = __float2bfloat16(o);
            g_xh[idx]  = h;
            g_xlo[idx] = __float2bfloat16(o - __bfloat162float(h));
        }
        __syncwarp();
    }
    __syncthreads();
    if (wid == 0) TC_DEALLOC(tmem, 256);
#else
    // Generic-arch fallback (not used at runtime on GB300; kept correct).
    const int tid = threadIdx.x;
    const int m0 = (blockIdx.x >> 2) * 128;
    const int n0 = (blockIdx.x & 3) * 256;
    for (int o = tid; o < 128 * 256; o += 256) {
        int row = o >> 8, cl = o & 255;
        int col = n0 + cl;
        const bf16* sh = g_sh + (size_t)(m0 + row) * ER;
        const bf16* sl = g_sl + (size_t)(m0 + row) * ER;
        const bf16* uv = g_U2 + (size_t)col * 768;
        float acc = 0.f;
        for (int k = 0; k < ER; k++) {
            float uh = __bfloat162float(uv[k]);
            float ul = __bfloat162float(uv[256 + k]);
            acc += __bfloat162float(sh[k]) * (uh + ul) + __bfloat162float(sl[k]) * uh;
        }
        const size_t idx = (size_t)(m0 + row) * Dd + col;
        float ov = fmaf(x0[idx], bias[col] + acc, xl_in[idx]);
        out[idx] = ov;
        bf16 h = __float2bfloat16(ov);
        g_xh[idx]  = h;
        g_xlo[idx] = __float2bfloat16(ov - __bfloat162float(h));
    }
#endif
}

// ---------------------------------------------------------------------------
// Launch
// ---------------------------------------------------------------------------
extern "C" void kernel_launch(void* const* d_in, const int* in_sizes, int n_in,
                              void* d_out, int out_size)
{
    const float* x    = (const float*)d_in[0];
    const float* U    = (const float*)d_in[1];
    const float* V    = (const float*)d_in[2];
    const float* C    = (const float*)d_in[3];
    const float* bias = (const float*)d_in[4];
    const float* gw   = (const float*)d_in[5];
    float* out = (float*)d_out;

    float* p_xl = nullptr;
    cudaGetSymbolAddress((void**)&p_xl, g_xl);

    const int smem_gate = (4 * Rr * CSTR + 8 * 256) * (int)sizeof(float);
    cudaFuncSetAttribute(gate_mix, cudaFuncAttributeMaxDynamicSharedMemorySize, smem_gate);
    cudaFuncSetAttribute(gemm1_tc, cudaFuncAttributeMaxDynamicSharedMemorySize, SM_TOTAL);
    cudaFuncSetAttribute(gemm2_tc, cudaFuncAttributeMaxDynamicSharedMemorySize, SM_TOTAL);

    const int EB = Ee * Rr * Dd;    // 262144

    conv_x<<<Bsz * Dd / 1024, 256>>>(x);

    for (int l = 0; l < Ll; l++) {
        const float* xin  = (l == 0)      ? x   : p_xl;
        float*       xout = (l == Ll - 1) ? out : p_xl;
        pack_V<<<3072, 256>>>(V + (size_t)l * EB);
        pack_U<<<3072, 256>>>(U + (size_t)l * EB);
        gemm1_tc<<<Bsz / 128, 256, SM_TOTAL>>>();
        gate_mix<<<Bsz / 8, 256, smem_gate>>>(xin, C + (size_t)l * Ee * Rr * Rr, gw);
        gemm2_tc<<<(Bsz / 128) * 4, 256, SM_TOTAL>>>(xin, x, bias + (size_t)l * Dd, xout);
    }
}